// round 14
// baseline (speedup 1.0000x reference)
#include <cuda_runtime.h>
#include <cuda_bf16.h>
#include <math.h>
#include <float.h>
#include <stdint.h>

#define Dm 1024
#define Sm 2048
#define Bm 2
#define Hm 16
#define DHm 64
#define BHm (Bm * Hm)

// Scratch (static device arrays; no allocations in kernel_launch)
__device__ __nv_bfloat16 g_xb[Bm * Sm * Dm];      // x in bf16
__device__ __nv_bfloat16 g_wqb[Dm * Dm];
__device__ __nv_bfloat16 g_wkb[Dm * Dm];
__device__ __nv_bfloat16 g_wvb[Dm * Dm];
__device__ __nv_bfloat16 g_wob[Dm * Dm];
__device__ __nv_bfloat16 g_q[BHm * Sm * DHm];     // [bh][s][d], pre-scaled by 1/8
__device__ __nv_bfloat16 g_k[BHm * Sm * DHm];     // [bh][s][d]
__device__ __nv_bfloat16 g_v[BHm * DHm * Sm];     // [bh][d][s]
__device__ __nv_bfloat16 g_ctx[Bm * Sm * Dm];     // [b][s][h*64+d]
__device__ float g_y[Bm * Sm * Dm];               // pre-LN residual sum (fp32)

// ---------------------------------------------------------------------------
// helpers
// ---------------------------------------------------------------------------
__device__ __forceinline__ uint32_t pack_bf16(float lo, float hi) {
    uint32_t r;
    asm("cvt.rn.bf16x2.f32 %0, %1, %2;" : "=r"(r) : "f"(hi), "f"(lo));
    return r;
}

__device__ __forceinline__ void mma_bf16(float c[4], const uint32_t a[4], const uint32_t b[2]) {
    asm volatile(
        "mma.sync.aligned.m16n8k16.row.col.f32.bf16.bf16.f32 "
        "{%0,%1,%2,%3}, {%4,%5,%6,%7}, {%8,%9}, {%0,%1,%2,%3};"
        : "+f"(c[0]), "+f"(c[1]), "+f"(c[2]), "+f"(c[3])
        : "r"(a[0]), "r"(a[1]), "r"(a[2]), "r"(a[3]), "r"(b[0]), "r"(b[1]));
}

__device__ __forceinline__ uint32_t cvta_s(const void* p) {
    return (uint32_t)__cvta_generic_to_shared(p);
}

#define LDSM4(R0, R1, R2, R3, ADDR) \
    asm volatile("ldmatrix.sync.aligned.m8n8.x4.shared.b16 {%0,%1,%2,%3}, [%4];" \
        : "=r"(R0), "=r"(R1), "=r"(R2), "=r"(R3) : "r"(ADDR))

#define CP16(DST, SRC) \
    asm volatile("cp.async.cg.shared.global [%0], [%1], 16;" :: "r"(DST), "l"(SRC))
#define CP_COMMIT() asm volatile("cp.async.commit_group;")
#define CP_WAIT0()  asm volatile("cp.async.wait_group 0;")
#define CP_WAIT1()  asm volatile("cp.async.wait_group 1;")

// ---------------------------------------------------------------------------
// fp32 -> bf16 bulk converts
// ---------------------------------------------------------------------------
__global__ void __launch_bounds__(256)
to_bf16_kernel(const float* __restrict__ src, __nv_bfloat16* __restrict__ dst, int n4)
{
    const int i = blockIdx.x * blockDim.x + threadIdx.x;
    if (i < n4) {
        const float4 v = ((const float4*)src)[i];
        uint2 w;
        w.x = pack_bf16(v.x, v.y);
        w.y = pack_bf16(v.z, v.w);
        ((uint2*)dst)[i] = w;
    }
}

__global__ void __launch_bounds__(256)
to_bf16_w4_kernel(const float* __restrict__ w0, const float* __restrict__ w1,
                  const float* __restrict__ w2, const float* __restrict__ w3,
                  __nv_bfloat16* __restrict__ d0, __nv_bfloat16* __restrict__ d1,
                  __nv_bfloat16* __restrict__ d2, __nv_bfloat16* __restrict__ d3,
                  int n4)
{
    const int z = blockIdx.z;
    const float* src = (z == 0) ? w0 : (z == 1) ? w1 : (z == 2) ? w2 : w3;
    __nv_bfloat16* dst = (z == 0) ? d0 : (z == 1) ? d1 : (z == 2) ? d2 : d3;
    const int i = blockIdx.x * blockDim.x + threadIdx.x;
    if (i < n4) {
        const float4 v = ((const float4*)src)[i];
        uint2 w;
        w.x = pack_bf16(v.x, v.y);
        w.y = pack_bf16(v.z, v.w);
        ((uint2*)dst)[i] = w;
    }
}

#define SSTR 20   // GEMM smem row stride in words (BK=32: 16 data words + 4 pad)
#define STG_WORDS (128 * SSTR)
#define GEMM_SMEM_BYTES (3 * STG_WORDS * 4 * 2)  // 61440

// ---------------------------------------------------------------------------
// bf16 GEMM mainloop (identical to measured R13): 3-stage cp.async + ldmatrix.
// ---------------------------------------------------------------------------
__device__ __forceinline__ void gemm_main_bf16(const __nv_bfloat16* __restrict__ A,
                                               const __nv_bfloat16* __restrict__ Wt,
                                               uint32_t* As, uint32_t* Bs,
                                               float acc[4][4][4])
{
    const int tid  = threadIdx.x;
    const int lane = tid & 31;
    const int warp = tid >> 5;
    const int wm   = (warp >> 2) * 64;
    const int wn   = (warp & 3) * 32;
    const int m0   = blockIdx.y * 128;
    const int n0   = blockIdx.x * 128;

    const int fr0 = tid >> 2;
    const int fr1 = (256 + tid) >> 2;
    const int fc  = tid & 3;

    const int a_row  = wm + (lane & 15);
    const int a_word = (lane >> 4) * 4;
    const int b_row  = wn + (lane & 7) + ((lane & 16) >> 1);
    const int b_word = (lane & 8) ? 4 : 0;

    uint32_t aaddr[3], baddr[3], sA0[3], sA1[3], sB0[3], sB1[3];
    #pragma unroll
    for (int s = 0; s < 3; ++s) {
        uint32_t* Asb = As + s * STG_WORDS;
        uint32_t* Bsb = Bs + s * STG_WORDS;
        aaddr[s] = cvta_s(&Asb[a_row * SSTR + a_word]);
        baddr[s] = cvta_s(&Bsb[b_row * SSTR + b_word]);
        sA0[s] = cvta_s(&Asb[fr0 * SSTR + fc * 4]);
        sA1[s] = cvta_s(&Asb[fr1 * SSTR + fc * 4]);
        sB0[s] = cvta_s(&Bsb[fr0 * SSTR + fc * 4]);
        sB1[s] = cvta_s(&Bsb[fr1 * SSTR + fc * 4]);
    }

    const __nv_bfloat16* Ap0 = A  + (size_t)(m0 + fr0) * Dm + fc * 8;
    const __nv_bfloat16* Ap1 = A  + (size_t)(m0 + fr1) * Dm + fc * 8;
    const __nv_bfloat16* Bp0 = Wt + (size_t)(n0 + fr0) * Dm + fc * 8;
    const __nv_bfloat16* Bp1 = Wt + (size_t)(n0 + fr1) * Dm + fc * 8;

    CP16(sA0[0], Ap0); CP16(sA1[0], Ap1);
    CP16(sB0[0], Bp0); CP16(sB1[0], Bp1);
    CP_COMMIT();
    CP16(sA0[1], Ap0 + 32); CP16(sA1[1], Ap1 + 32);
    CP16(sB0[1], Bp0 + 32); CP16(sB1[1], Bp1 + 32);
    CP_COMMIT();

    int cur = 0;
    for (int kt = 0; kt < 32; ++kt) {
        if (kt < 31) CP_WAIT1(); else CP_WAIT0();
        __syncthreads();

        if (kt + 2 <= 31) {
            int nxt = cur + 2; if (nxt >= 3) nxt -= 3;
            const int kb = (kt + 2) * 32;
            CP16(sA0[nxt], Ap0 + kb); CP16(sA1[nxt], Ap1 + kb);
            CP16(sB0[nxt], Bp0 + kb); CP16(sB1[nxt], Bp1 + kb);
            CP_COMMIT();
        }

        #pragma unroll
        for (int slab = 0; slab < 2; ++slab) {
            const uint32_t soff = slab * 8 * 4;
            uint32_t a[4][4], b[4][2];
            #pragma unroll
            for (int mi = 0; mi < 4; ++mi)
                LDSM4(a[mi][0], a[mi][1], a[mi][2], a[mi][3],
                      aaddr[cur] + (mi * 16 * SSTR) * 4 + soff);
            #pragma unroll
            for (int n2 = 0; n2 < 2; ++n2)
                LDSM4(b[2 * n2][0], b[2 * n2][1], b[2 * n2 + 1][0], b[2 * n2 + 1][1],
                      baddr[cur] + (n2 * 16 * SSTR) * 4 + soff);
            #pragma unroll
            for (int mi = 0; mi < 4; ++mi)
                #pragma unroll
                for (int ni = 0; ni < 4; ++ni)
                    mma_bf16(acc[mi][ni], a[mi], b[ni]);
        }

        if (++cur == 3) cur = 0;
    }
}

// ---------------------------------------------------------------------------
// QKV projection. grid = (8, 32, 3).
// ---------------------------------------------------------------------------
__global__ void __launch_bounds__(256)
gemm_qkv_kernel(const float* __restrict__ bq, const float* __restrict__ bk,
                const float* __restrict__ bv)
{
    extern __shared__ uint32_t dyn_smem[];
    uint32_t* As = dyn_smem;
    uint32_t* Bs = dyn_smem + 3 * STG_WORDS;

    const int z = blockIdx.z;
    const __nv_bfloat16* W = (z == 0) ? g_wqb : (z == 1) ? g_wkb : g_wvb;
    const float* bias      = (z == 0) ? bq : (z == 1) ? bk : bv;

    float acc[4][4][4];
    #pragma unroll
    for (int mi = 0; mi < 4; ++mi)
        #pragma unroll
        for (int ni = 0; ni < 4; ++ni) {
            acc[mi][ni][0] = 0.f; acc[mi][ni][1] = 0.f;
            acc[mi][ni][2] = 0.f; acc[mi][ni][3] = 0.f;
        }

    gemm_main_bf16(g_xb, W, As, Bs, acc);

    const int tid  = threadIdx.x;
    const int lane = tid & 31;
    const int warp = tid >> 5;
    const int wm   = (warp >> 2) * 64;
    const int wn   = (warp & 3) * 32;
    const int g    = lane >> 2;
    const int q    = lane & 3;
    const int m0   = blockIdx.y * 128;
    const int n0   = blockIdx.x * 128;

    if (z < 2) {
        __nv_bfloat16* dst = (z == 0) ? g_q : g_k;
        const float sc = (z == 0) ? 0.125f : 1.0f;
        #pragma unroll
        for (int mi = 0; mi < 4; ++mi) {
            #pragma unroll
            for (int i = 0; i < 2; ++i) {
                const int gm = m0 + wm + mi * 16 + g + i * 8;
                const int b  = gm >> 11;
                const int s  = gm & 2047;
                #pragma unroll
                for (int ni = 0; ni < 4; ++ni) {
                    const int gn0 = n0 + wn + ni * 8 + q * 2;
                    const int h   = gn0 >> 6, dd0 = gn0 & 63;
                    const uint32_t w = pack_bf16((acc[mi][ni][i * 2 + 0] + bias[gn0 + 0]) * sc,
                                                 (acc[mi][ni][i * 2 + 1] + bias[gn0 + 1]) * sc);
                    *(uint32_t*)&dst[(((size_t)(b * Hm + h) * Sm + s) * DHm) + dd0] = w;
                }
            }
        }
    } else {
        #pragma unroll
        for (int mi = 0; mi < 4; ++mi) {
            #pragma unroll
            for (int i = 0; i < 2; ++i) {
                const int gm = m0 + wm + mi * 16 + g + i * 8;
                const int b  = gm >> 11;
                const int s  = gm & 2047;
                #pragma unroll
                for (int ni = 0; ni < 4; ++ni) {
                    const int gn0 = n0 + wn + ni * 8 + q * 2;
                    const int h   = gn0 >> 6, dd0 = gn0 & 63;
                    const size_t base = ((size_t)(b * Hm + h) * DHm + dd0) * Sm + s;
                    g_v[base]      = __float2bfloat16_rn(acc[mi][ni][i * 2 + 0] + bias[gn0 + 0]);
                    g_v[base + Sm] = __float2bfloat16_rn(acc[mi][ni][i * 2 + 1] + bias[gn0 + 1]);
                }
            }
        }
    }
}

// ---------------------------------------------------------------------------
// Output projection + residual: y = ctx @ Wo^T + bo + x
// ---------------------------------------------------------------------------
__global__ void __launch_bounds__(256)
gemm_oproj_kernel(const float* __restrict__ bo, const float* __restrict__ x)
{
    extern __shared__ uint32_t dyn_smem[];
    uint32_t* As = dyn_smem;
    uint32_t* Bs = dyn_smem + 3 * STG_WORDS;

    float acc[4][4][4];
    #pragma unroll
    for (int mi = 0; mi < 4; ++mi)
        #pragma unroll
        for (int ni = 0; ni < 4; ++ni) {
            acc[mi][ni][0] = 0.f; acc[mi][ni][1] = 0.f;
            acc[mi][ni][2] = 0.f; acc[mi][ni][3] = 0.f;
        }

    gemm_main_bf16(g_ctx, g_wob, As, Bs, acc);

    const int tid  = threadIdx.x;
    const int lane = tid & 31;
    const int warp = tid >> 5;
    const int wm   = (warp >> 2) * 64;
    const int wn   = (warp & 3) * 32;
    const int g    = lane >> 2;
    const int q    = lane & 3;
    const int m0   = blockIdx.y * 128;
    const int n0   = blockIdx.x * 128;

    #pragma unroll
    for (int mi = 0; mi < 4; ++mi) {
        #pragma unroll
        for (int i = 0; i < 2; ++i) {
            const int gm = m0 + wm + mi * 16 + g + i * 8;
            #pragma unroll
            for (int ni = 0; ni < 4; ++ni) {
                const int gn0 = n0 + wn + ni * 8 + q * 2;
                const size_t off = (size_t)gm * Dm + gn0;
                const float2 r = *(const float2*)&x[off];
                float2 v;
                v.x = acc[mi][ni][i * 2 + 0] + bo[gn0 + 0] + r.x;
                v.y = acc[mi][ni][i * 2 + 1] + bo[gn0 + 1] + r.y;
                *(float2*)&g_y[off] = v;
            }
        }
    }
}

// ---------------------------------------------------------------------------
// Causal flash attention, 128-row q-tiles, double-buffered K/V via cp.async.
// grid = (16, 32), 256 thr. Dynamic smem: Ks[2], Vt[2], Ps = 55296 B.
// ---------------------------------------------------------------------------
#define ALD 36
#define KV_WORDS (64 * ALD)
#define ATTN_SMEM_BYTES ((4 * KV_WORDS + 128 * ALD) * 4)   // 55296

__global__ void __launch_bounds__(256)
attn_kernel(const __nv_bfloat16* __restrict__ Qg, const __nv_bfloat16* __restrict__ Kg,
            const __nv_bfloat16* __restrict__ Vg, __nv_bfloat16* __restrict__ ctx)
{
    extern __shared__ uint32_t asmem[];
    uint32_t* KsB[2] = { asmem,                asmem + KV_WORDS };
    uint32_t* VtB[2] = { asmem + 2 * KV_WORDS, asmem + 3 * KV_WORDS };
    uint32_t* Ps     = asmem + 4 * KV_WORDS;

    const int tid  = threadIdx.x;
    const int lane = tid & 31;
    const int warp = tid >> 5;
    const int g    = lane >> 2;
    const int q    = lane & 3;
    const int bh   = blockIdx.y;
    const int qb   = (int)(gridDim.x - 1) - (int)blockIdx.x;   // heavy first
    const int qi0  = qb * 128;
    const int wrow = warp * 16;

    const __nv_bfloat16* Qbh = Qg + (size_t)bh * Sm * DHm;
    const __nv_bfloat16* Kbh = Kg + (size_t)bh * Sm * DHm;
    const __nv_bfloat16* Vbh = Vg + (size_t)bh * DHm * Sm;

    // ldmatrix base addresses per buffer
    const int fr_row = (lane & 7) + ((lane & 16) >> 1);
    const int fr_wrd = (lane & 8) ? 4 : 0;
    uint32_t ks_b[2], vt_b[2];
    #pragma unroll
    for (int s = 0; s < 2; ++s) {
        ks_b[s] = cvta_s(&KsB[s][fr_row * ALD + fr_wrd]);
        vt_b[s] = cvta_s(&VtB[s][fr_row * ALD + fr_wrd]);
    }
    const uint32_t p_a = cvta_s(&Ps[(wrow + (lane & 15)) * ALD + (lane >> 4) * 4]);

    // cp.async fill positions (2 K + 2 V chunks per thread per tile)
    const int f_row0 = tid >> 3;            // rows 0..31
    const int f_row1 = (256 + tid) >> 3;    // rows 32..63
    const int f_cw   = tid & 7;
    uint32_t kdst[2][2], vdst[2][2];
    #pragma unroll
    for (int s = 0; s < 2; ++s) {
        kdst[s][0] = cvta_s(&KsB[s][f_row0 * ALD + f_cw * 4]);
        kdst[s][1] = cvta_s(&KsB[s][f_row1 * ALD + f_cw * 4]);
        vdst[s][0] = cvta_s(&VtB[s][f_row0 * ALD + f_cw * 4]);
        vdst[s][1] = cvta_s(&VtB[s][f_row1 * ALD + f_cw * 4]);
    }

    // Q fragments (already scaled by 1/8)
    uint32_t qa[4][4];
    {
        const size_t r0 = (size_t)(qi0 + wrow + g) * DHm;
        const size_t r1 = r0 + 8 * DHm;
        #pragma unroll
        for (int kf = 0; kf < 4; ++kf) {
            const int d0 = kf * 16 + 2 * q;
            qa[kf][0] = *(const uint32_t*)&Qbh[r0 + d0];
            qa[kf][1] = *(const uint32_t*)&Qbh[r1 + d0];
            qa[kf][2] = *(const uint32_t*)&Qbh[r0 + d0 + 8];
            qa[kf][3] = *(const uint32_t*)&Qbh[r1 + d0 + 8];
        }
    }

    float m0 = -1e30f, m1 = -1e30f, l0 = 0.f, l1 = 0.f;
    float o[8][4];
    #pragma unroll
    for (int nf = 0; nf < 8; ++nf) {
        o[nf][0] = 0.f; o[nf][1] = 0.f; o[nf][2] = 0.f; o[nf][3] = 0.f;
    }

    const int ntiles = 2 * qb + 2;

    // prologue: fill tile 0 into buffer 0
    {
        CP16(kdst[0][0], Kbh + (size_t)f_row0 * DHm + f_cw * 8);
        CP16(kdst[0][1], Kbh + (size_t)f_row1 * DHm + f_cw * 8);
        CP16(vdst[0][0], Vbh + (size_t)f_row0 * Sm + f_cw * 8);
        CP16(vdst[0][1], Vbh + (size_t)f_row1 * Sm + f_cw * 8);
        CP_COMMIT();
    }

    for (int kt = 0; kt < ntiles; ++kt) {
        const int cur = kt & 1;
        CP_WAIT0();
        __syncthreads();   // data visible; prior reads of the other buffer done

        if (kt + 1 < ntiles) {
            const int nxt = cur ^ 1;
            const int kj1 = (kt + 1) * 64;
            CP16(kdst[nxt][0], Kbh + (size_t)(kj1 + f_row0) * DHm + f_cw * 8);
            CP16(kdst[nxt][1], Kbh + (size_t)(kj1 + f_row1) * DHm + f_cw * 8);
            CP16(vdst[nxt][0], Vbh + (size_t)f_row0 * Sm + kj1 + f_cw * 8);
            CP16(vdst[nxt][1], Vbh + (size_t)f_row1 * Sm + kj1 + f_cw * 8);
            CP_COMMIT();
        }

        const int kj0 = kt * 64;

        // S = Q K^T  (per warp: 16 x 64)
        float sacc[8][4];
        #pragma unroll
        for (int nf = 0; nf < 8; ++nf) {
            sacc[nf][0] = 0.f; sacc[nf][1] = 0.f; sacc[nf][2] = 0.f; sacc[nf][3] = 0.f;
        }
        #pragma unroll
        for (int kf = 0; kf < 4; ++kf) {
            #pragma unroll
            for (int n2 = 0; n2 < 4; ++n2) {
                uint32_t b4[4];
                LDSM4(b4[0], b4[1], b4[2], b4[3],
                      ks_b[cur] + (n2 * 16 * ALD + kf * 8) * 4);
                mma_bf16(sacc[2 * n2],     qa[kf], b4);
                mma_bf16(sacc[2 * n2 + 1], qa[kf], b4 + 2);
            }
        }

        // causal mask (only last two tiles can be partial)
        if (kt >= 2 * qb) {
            const int rg0 = qi0 + wrow + g, rg1 = rg0 + 8;
            #pragma unroll
            for (int nf = 0; nf < 8; ++nf) {
                const int cg = kj0 + nf * 8 + 2 * q;
                if (cg     > rg0) sacc[nf][0] = -1e30f;
                if (cg + 1 > rg0) sacc[nf][1] = -1e30f;
                if (cg     > rg1) sacc[nf][2] = -1e30f;
                if (cg + 1 > rg1) sacc[nf][3] = -1e30f;
            }
        }

        // online softmax
        float mx0 = -1e30f, mx1 = -1e30f;
        #pragma unroll
        for (int nf = 0; nf < 8; ++nf) {
            mx0 = fmaxf(mx0, fmaxf(sacc[nf][0], sacc[nf][1]));
            mx1 = fmaxf(mx1, fmaxf(sacc[nf][2], sacc[nf][3]));
        }
        mx0 = fmaxf(mx0, __shfl_xor_sync(0xffffffffu, mx0, 1));
        mx0 = fmaxf(mx0, __shfl_xor_sync(0xffffffffu, mx0, 2));
        mx1 = fmaxf(mx1, __shfl_xor_sync(0xffffffffu, mx1, 1));
        mx1 = fmaxf(mx1, __shfl_xor_sync(0xffffffffu, mx1, 2));

        const float mn0 = fmaxf(m0, mx0);
        const float mn1 = fmaxf(m1, mx1);
        const float al0 = __expf(m0 - mn0);
        const float al1 = __expf(m1 - mn1);
        m0 = mn0; m1 = mn1;

        float rs0 = 0.f, rs1 = 0.f;
        #pragma unroll
        for (int nf = 0; nf < 8; ++nf) {
            sacc[nf][0] = __expf(sacc[nf][0] - mn0);
            sacc[nf][1] = __expf(sacc[nf][1] - mn0);
            sacc[nf][2] = __expf(sacc[nf][2] - mn1);
            sacc[nf][3] = __expf(sacc[nf][3] - mn1);
            rs0 += sacc[nf][0] + sacc[nf][1];
            rs1 += sacc[nf][2] + sacc[nf][3];
        }
        rs0 += __shfl_xor_sync(0xffffffffu, rs0, 1);
        rs0 += __shfl_xor_sync(0xffffffffu, rs0, 2);
        rs1 += __shfl_xor_sync(0xffffffffu, rs1, 1);
        rs1 += __shfl_xor_sync(0xffffffffu, rs1, 2);

        l0 = l0 * al0 + rs0;
        l1 = l1 * al1 + rs1;
        #pragma unroll
        for (int nf = 0; nf < 8; ++nf) {
            o[nf][0] *= al0; o[nf][1] *= al0;
            o[nf][2] *= al1; o[nf][3] *= al1;
        }

        // store P into warp-private rows of Ps
        {
            const int r0l = wrow + g, r1l = r0l + 8;
            #pragma unroll
            for (int nf = 0; nf < 8; ++nf) {
                Ps[r0l * ALD + nf * 4 + q] = pack_bf16(sacc[nf][0], sacc[nf][1]);
                Ps[r1l * ALD + nf * 4 + q] = pack_bf16(sacc[nf][2], sacc[nf][3]);
            }
        }
        __syncwarp();

        // O += P @ V
        #pragma unroll
        for (int kf = 0; kf < 4; ++kf) {
            uint32_t a4[4];
            LDSM4(a4[0], a4[1], a4[2], a4[3], p_a + (kf * 8) * 4);
            #pragma unroll
            for (int n2 = 0; n2 < 4; ++n2) {
                uint32_t b4[4];
                LDSM4(b4[0], b4[1], b4[2], b4[3],
                      vt_b[cur] + (n2 * 16 * ALD + kf * 8) * 4);
                mma_bf16(o[2 * n2],     a4, b4);
                mma_bf16(o[2 * n2 + 1], a4, b4 + 2);
            }
        }
    }

    // epilogue
    const int b = bh >> 4, h = bh & 15;
    const float inv0 = 1.0f / l0;
    const float inv1 = 1.0f / l1;
    const int s0 = qi0 + wrow + g;
    #pragma unroll
    for (int nf = 0; nf < 8; ++nf) {
        const int dd = h * DHm + nf * 8 + 2 * q;
        *(uint32_t*)&ctx[((size_t)(b * Sm + s0)) * Dm + dd] =
            pack_bf16(o[nf][0] * inv0, o[nf][1] * inv0);
        *(uint32_t*)&ctx[((size_t)(b * Sm + s0 + 8)) * Dm + dd] =
            pack_bf16(o[nf][2] * inv1, o[nf][3] * inv1);
    }
}

// ---------------------------------------------------------------------------
// LayerNorm over last dim (1024).
// ---------------------------------------------------------------------------
__global__ void __launch_bounds__(256)
ln_kernel(const float* __restrict__ y, const float* __restrict__ gam,
          const float* __restrict__ bet, float* __restrict__ out)
{
    __shared__ float red[2][8];
    const int row = blockIdx.x;
    const int tid = threadIdx.x;

    const float4 v = *(const float4*)&y[(size_t)row * Dm + tid * 4];
    float s  = v.x + v.y + v.z + v.w;
    float ss = v.x * v.x + v.y * v.y + v.z * v.z + v.w * v.w;

    #pragma unroll
    for (int off = 16; off > 0; off >>= 1) {
        s  += __shfl_xor_sync(0xffffffffu, s, off);
        ss += __shfl_xor_sync(0xffffffffu, ss, off);
    }
    const int wid = tid >> 5, lane = tid & 31;
    if (lane == 0) { red[0][wid] = s; red[1][wid] = ss; }
    __syncthreads();
    if (tid == 0) {
        float S = 0.f, SS = 0.f;
        #pragma unroll
        for (int w = 0; w < 8; ++w) { S += red[0][w]; SS += red[1][w]; }
        red[0][0] = S; red[1][0] = SS;
    }
    __syncthreads();

    const float mu   = red[0][0] * (1.0f / Dm);
    const float var  = red[1][0] * (1.0f / Dm) - mu * mu;
    const float rstd = rsqrtf(var + 1e-5f);

    const float4 g4 = *(const float4*)&gam[tid * 4];
    const float4 b4 = *(const float4*)&bet[tid * 4];
    float4 r;
    r.x = (v.x - mu) * rstd * g4.x + b4.x;
    r.y = (v.y - mu) * rstd * g4.y + b4.y;
    r.z = (v.z - mu) * rstd * g4.z + b4.z;
    r.w = (v.w - mu) * rstd * g4.w + b4.w;
    *(float4*)&out[(size_t)row * Dm + tid * 4] = r;
}

// ---------------------------------------------------------------------------
extern "C" void kernel_launch(void* const* d_in, const int* in_sizes, int n_in,
                              void* d_out, int out_size)
{
    const float* x    = (const float*)d_in[0];
    const float* Wq   = (const float*)d_in[1];
    const float* bq   = (const float*)d_in[2];
    const float* Wk   = (const float*)d_in[3];
    const float* bk   = (const float*)d_in[4];
    const float* Wv   = (const float*)d_in[5];
    const float* bv   = (const float*)d_in[6];
    const float* Wo   = (const float*)d_in[7];
    const float* bo   = (const float*)d_in[8];
    const float* ln_g = (const float*)d_in[9];
    const float* ln_b = (const float*)d_in[10];
    float* out = (float*)d_out;

    __nv_bfloat16 *xb_p, *wq_p, *wk_p, *wv_p, *wo_p, *q_p, *k_p, *v_p, *ctx_p;
    float* y_p;
    cudaGetSymbolAddress((void**)&xb_p,  g_xb);
    cudaGetSymbolAddress((void**)&wq_p,  g_wqb);
    cudaGetSymbolAddress((void**)&wk_p,  g_wkb);
    cudaGetSymbolAddress((void**)&wv_p,  g_wvb);
    cudaGetSymbolAddress((void**)&wo_p,  g_wob);
    cudaGetSymbolAddress((void**)&q_p,   g_q);
    cudaGetSymbolAddress((void**)&k_p,   g_k);
    cudaGetSymbolAddress((void**)&v_p,   g_v);
    cudaGetSymbolAddress((void**)&ctx_p, g_ctx);
    cudaGetSymbolAddress((void**)&y_p,   g_y);

    cudaFuncSetAttribute(gemm_qkv_kernel,
                         cudaFuncAttributeMaxDynamicSharedMemorySize, GEMM_SMEM_BYTES);
    cudaFuncSetAttribute(gemm_oproj_kernel,
                         cudaFuncAttributeMaxDynamicSharedMemorySize, GEMM_SMEM_BYTES);
    cudaFuncSetAttribute(attn_kernel,
                         cudaFuncAttributeMaxDynamicSharedMemorySize, ATTN_SMEM_BYTES);

    const int nx4 = Bm * Sm * Dm / 4;
    const int nw4 = Dm * Dm / 4;
    to_bf16_kernel<<<(nx4 + 255) / 256, 256>>>(x, xb_p, nx4);
    to_bf16_w4_kernel<<<dim3((nw4 + 255) / 256, 1, 4), 256>>>(
        Wq, Wk, Wv, Wo, wq_p, wk_p, wv_p, wo_p, nw4);

    gemm_qkv_kernel<<<dim3(8, 32, 3), 256, GEMM_SMEM_BYTES>>>(bq, bk, bv);
    attn_kernel<<<dim3(16, 32), 256, ATTN_SMEM_BYTES>>>(q_p, k_p, v_p, ctx_p);
    gemm_oproj_kernel<<<dim3(8, 32), 256, GEMM_SMEM_BYTES>>>(bo, x);
    ln_kernel<<<4096, 256>>>(y_p, ln_g, ln_b, out);
}

// round 15
// speedup vs baseline: 1.0663x; 1.0663x over previous
#include <cuda_runtime.h>
#include <cuda_bf16.h>
#include <math.h>
#include <float.h>
#include <stdint.h>

#define Dm 1024
#define Sm 2048
#define Bm 2
#define Hm 16
#define DHm 64
#define BHm (Bm * Hm)

// Scratch (static device arrays; no allocations in kernel_launch)
__device__ __nv_bfloat16 g_xb[Bm * Sm * Dm];      // x in bf16
__device__ __nv_bfloat16 g_wqb[Dm * Dm];
__device__ __nv_bfloat16 g_wkb[Dm * Dm];
__device__ __nv_bfloat16 g_wvb[Dm * Dm];
__device__ __nv_bfloat16 g_wob[Dm * Dm];
__device__ __nv_bfloat16 g_q[BHm * Sm * DHm];     // [bh][s][d], pre-scaled by log2e/8
__device__ __nv_bfloat16 g_k[BHm * Sm * DHm];     // [bh][s][d]
__device__ __nv_bfloat16 g_v[BHm * DHm * Sm];     // [bh][d][s]
__device__ __nv_bfloat16 g_ctx[Bm * Sm * Dm];     // [b][s][h*64+d]
__device__ float g_y[Bm * Sm * Dm];               // pre-LN residual sum (fp32)

// ---------------------------------------------------------------------------
// helpers
// ---------------------------------------------------------------------------
__device__ __forceinline__ uint32_t pack_bf16(float lo, float hi) {
    uint32_t r;
    asm("cvt.rn.bf16x2.f32 %0, %1, %2;" : "=r"(r) : "f"(hi), "f"(lo));
    return r;
}

__device__ __forceinline__ float ex2f(float x) {
    float r;
    asm("ex2.approx.ftz.f32 %0, %1;" : "=f"(r) : "f"(x));
    return r;
}

__device__ __forceinline__ void mma_bf16(float c[4], const uint32_t a[4], const uint32_t b[2]) {
    asm volatile(
        "mma.sync.aligned.m16n8k16.row.col.f32.bf16.bf16.f32 "
        "{%0,%1,%2,%3}, {%4,%5,%6,%7}, {%8,%9}, {%0,%1,%2,%3};"
        : "+f"(c[0]), "+f"(c[1]), "+f"(c[2]), "+f"(c[3])
        : "r"(a[0]), "r"(a[1]), "r"(a[2]), "r"(a[3]), "r"(b[0]), "r"(b[1]));
}

__device__ __forceinline__ uint32_t cvta_s(const void* p) {
    return (uint32_t)__cvta_generic_to_shared(p);
}

#define LDSM4(R0, R1, R2, R3, ADDR) \
    asm volatile("ldmatrix.sync.aligned.m8n8.x4.shared.b16 {%0,%1,%2,%3}, [%4];" \
        : "=r"(R0), "=r"(R1), "=r"(R2), "=r"(R3) : "r"(ADDR))

#define CP16(DST, SRC) \
    asm volatile("cp.async.cg.shared.global [%0], [%1], 16;" :: "r"(DST), "l"(SRC))
#define CP_COMMIT() asm volatile("cp.async.commit_group;")
#define CP_WAIT0()  asm volatile("cp.async.wait_group 0;")
#define CP_WAIT1()  asm volatile("cp.async.wait_group 1;")

// ---------------------------------------------------------------------------
// fp32 -> bf16 bulk converts
// ---------------------------------------------------------------------------
__global__ void __launch_bounds__(256)
to_bf16_kernel(const float* __restrict__ src, __nv_bfloat16* __restrict__ dst, int n4)
{
    const int i = blockIdx.x * blockDim.x + threadIdx.x;
    if (i < n4) {
        const float4 v = ((const float4*)src)[i];
        uint2 w;
        w.x = pack_bf16(v.x, v.y);
        w.y = pack_bf16(v.z, v.w);
        ((uint2*)dst)[i] = w;
    }
}

__global__ void __launch_bounds__(256)
to_bf16_w4_kernel(const float* __restrict__ w0, const float* __restrict__ w1,
                  const float* __restrict__ w2, const float* __restrict__ w3,
                  __nv_bfloat16* __restrict__ d0, __nv_bfloat16* __restrict__ d1,
                  __nv_bfloat16* __restrict__ d2, __nv_bfloat16* __restrict__ d3,
                  int n4)
{
    const int z = blockIdx.z;
    const float* src = (z == 0) ? w0 : (z == 1) ? w1 : (z == 2) ? w2 : w3;
    __nv_bfloat16* dst = (z == 0) ? d0 : (z == 1) ? d1 : (z == 2) ? d2 : d3;
    const int i = blockIdx.x * blockDim.x + threadIdx.x;
    if (i < n4) {
        const float4 v = ((const float4*)src)[i];
        uint2 w;
        w.x = pack_bf16(v.x, v.y);
        w.y = pack_bf16(v.z, v.w);
        ((uint2*)dst)[i] = w;
    }
}

#define SSTR 20   // GEMM smem row stride in words (BK=32: 16 data words + 4 pad)
#define STG_WORDS (128 * SSTR)
#define GEMM_SMEM_BYTES (3 * STG_WORDS * 4 * 2)  // 61440

// ---------------------------------------------------------------------------
// bf16 GEMM mainloop (identical to measured R13): 3-stage cp.async + ldmatrix.
// ---------------------------------------------------------------------------
__device__ __forceinline__ void gemm_main_bf16(const __nv_bfloat16* __restrict__ A,
                                               const __nv_bfloat16* __restrict__ Wt,
                                               uint32_t* As, uint32_t* Bs,
                                               float acc[4][4][4])
{
    const int tid  = threadIdx.x;
    const int lane = tid & 31;
    const int warp = tid >> 5;
    const int wm   = (warp >> 2) * 64;
    const int wn   = (warp & 3) * 32;
    const int m0   = blockIdx.y * 128;
    const int n0   = blockIdx.x * 128;

    const int fr0 = tid >> 2;
    const int fr1 = (256 + tid) >> 2;
    const int fc  = tid & 3;

    const int a_row  = wm + (lane & 15);
    const int a_word = (lane >> 4) * 4;
    const int b_row  = wn + (lane & 7) + ((lane & 16) >> 1);
    const int b_word = (lane & 8) ? 4 : 0;

    uint32_t aaddr[3], baddr[3], sA0[3], sA1[3], sB0[3], sB1[3];
    #pragma unroll
    for (int s = 0; s < 3; ++s) {
        uint32_t* Asb = As + s * STG_WORDS;
        uint32_t* Bsb = Bs + s * STG_WORDS;
        aaddr[s] = cvta_s(&Asb[a_row * SSTR + a_word]);
        baddr[s] = cvta_s(&Bsb[b_row * SSTR + b_word]);
        sA0[s] = cvta_s(&Asb[fr0 * SSTR + fc * 4]);
        sA1[s] = cvta_s(&Asb[fr1 * SSTR + fc * 4]);
        sB0[s] = cvta_s(&Bsb[fr0 * SSTR + fc * 4]);
        sB1[s] = cvta_s(&Bsb[fr1 * SSTR + fc * 4]);
    }

    const __nv_bfloat16* Ap0 = A  + (size_t)(m0 + fr0) * Dm + fc * 8;
    const __nv_bfloat16* Ap1 = A  + (size_t)(m0 + fr1) * Dm + fc * 8;
    const __nv_bfloat16* Bp0 = Wt + (size_t)(n0 + fr0) * Dm + fc * 8;
    const __nv_bfloat16* Bp1 = Wt + (size_t)(n0 + fr1) * Dm + fc * 8;

    CP16(sA0[0], Ap0); CP16(sA1[0], Ap1);
    CP16(sB0[0], Bp0); CP16(sB1[0], Bp1);
    CP_COMMIT();
    CP16(sA0[1], Ap0 + 32); CP16(sA1[1], Ap1 + 32);
    CP16(sB0[1], Bp0 + 32); CP16(sB1[1], Bp1 + 32);
    CP_COMMIT();

    int cur = 0;
    for (int kt = 0; kt < 32; ++kt) {
        if (kt < 31) CP_WAIT1(); else CP_WAIT0();
        __syncthreads();

        if (kt + 2 <= 31) {
            int nxt = cur + 2; if (nxt >= 3) nxt -= 3;
            const int kb = (kt + 2) * 32;
            CP16(sA0[nxt], Ap0 + kb); CP16(sA1[nxt], Ap1 + kb);
            CP16(sB0[nxt], Bp0 + kb); CP16(sB1[nxt], Bp1 + kb);
            CP_COMMIT();
        }

        #pragma unroll
        for (int slab = 0; slab < 2; ++slab) {
            const uint32_t soff = slab * 8 * 4;
            uint32_t a[4][4], b[4][2];
            #pragma unroll
            for (int mi = 0; mi < 4; ++mi)
                LDSM4(a[mi][0], a[mi][1], a[mi][2], a[mi][3],
                      aaddr[cur] + (mi * 16 * SSTR) * 4 + soff);
            #pragma unroll
            for (int n2 = 0; n2 < 2; ++n2)
                LDSM4(b[2 * n2][0], b[2 * n2][1], b[2 * n2 + 1][0], b[2 * n2 + 1][1],
                      baddr[cur] + (n2 * 16 * SSTR) * 4 + soff);
            #pragma unroll
            for (int mi = 0; mi < 4; ++mi)
                #pragma unroll
                for (int ni = 0; ni < 4; ++ni)
                    mma_bf16(acc[mi][ni], a[mi], b[ni]);
        }

        if (++cur == 3) cur = 0;
    }
}

// ---------------------------------------------------------------------------
// QKV projection. grid = (8, 32, 3). Q pre-scaled by log2e/8.
// ---------------------------------------------------------------------------
__global__ void __launch_bounds__(256)
gemm_qkv_kernel(const float* __restrict__ bq, const float* __restrict__ bk,
                const float* __restrict__ bv)
{
    extern __shared__ uint32_t dyn_smem[];
    uint32_t* As = dyn_smem;
    uint32_t* Bs = dyn_smem + 3 * STG_WORDS;

    const int z = blockIdx.z;
    const __nv_bfloat16* W = (z == 0) ? g_wqb : (z == 1) ? g_wkb : g_wvb;
    const float* bias      = (z == 0) ? bq : (z == 1) ? bk : bv;

    float acc[4][4][4];
    #pragma unroll
    for (int mi = 0; mi < 4; ++mi)
        #pragma unroll
        for (int ni = 0; ni < 4; ++ni) {
            acc[mi][ni][0] = 0.f; acc[mi][ni][1] = 0.f;
            acc[mi][ni][2] = 0.f; acc[mi][ni][3] = 0.f;
        }

    gemm_main_bf16(g_xb, W, As, Bs, acc);

    const int tid  = threadIdx.x;
    const int lane = tid & 31;
    const int warp = tid >> 5;
    const int wm   = (warp >> 2) * 64;
    const int wn   = (warp & 3) * 32;
    const int g    = lane >> 2;
    const int q    = lane & 3;
    const int m0   = blockIdx.y * 128;
    const int n0   = blockIdx.x * 128;

    if (z < 2) {
        __nv_bfloat16* dst = (z == 0) ? g_q : g_k;
        const float sc = (z == 0) ? (0.125f * 1.4426950408889634f) : 1.0f;
        #pragma unroll
        for (int mi = 0; mi < 4; ++mi) {
            #pragma unroll
            for (int i = 0; i < 2; ++i) {
                const int gm = m0 + wm + mi * 16 + g + i * 8;
                const int b  = gm >> 11;
                const int s  = gm & 2047;
                #pragma unroll
                for (int ni = 0; ni < 4; ++ni) {
                    const int gn0 = n0 + wn + ni * 8 + q * 2;
                    const int h   = gn0 >> 6, dd0 = gn0 & 63;
                    const uint32_t w = pack_bf16((acc[mi][ni][i * 2 + 0] + bias[gn0 + 0]) * sc,
                                                 (acc[mi][ni][i * 2 + 1] + bias[gn0 + 1]) * sc);
                    *(uint32_t*)&dst[(((size_t)(b * Hm + h) * Sm + s) * DHm) + dd0] = w;
                }
            }
        }
    } else {
        #pragma unroll
        for (int mi = 0; mi < 4; ++mi) {
            #pragma unroll
            for (int i = 0; i < 2; ++i) {
                const int gm = m0 + wm + mi * 16 + g + i * 8;
                const int b  = gm >> 11;
                const int s  = gm & 2047;
                #pragma unroll
                for (int ni = 0; ni < 4; ++ni) {
                    const int gn0 = n0 + wn + ni * 8 + q * 2;
                    const int h   = gn0 >> 6, dd0 = gn0 & 63;
                    const size_t base = ((size_t)(b * Hm + h) * DHm + dd0) * Sm + s;
                    g_v[base]      = __float2bfloat16_rn(acc[mi][ni][i * 2 + 0] + bias[gn0 + 0]);
                    g_v[base + Sm] = __float2bfloat16_rn(acc[mi][ni][i * 2 + 1] + bias[gn0 + 1]);
                }
            }
        }
    }
}

// ---------------------------------------------------------------------------
// Output projection + residual: y = ctx @ Wo^T + bo + x
// ---------------------------------------------------------------------------
__global__ void __launch_bounds__(256)
gemm_oproj_kernel(const float* __restrict__ bo, const float* __restrict__ x)
{
    extern __shared__ uint32_t dyn_smem[];
    uint32_t* As = dyn_smem;
    uint32_t* Bs = dyn_smem + 3 * STG_WORDS;

    float acc[4][4][4];
    #pragma unroll
    for (int mi = 0; mi < 4; ++mi)
        #pragma unroll
        for (int ni = 0; ni < 4; ++ni) {
            acc[mi][ni][0] = 0.f; acc[mi][ni][1] = 0.f;
            acc[mi][ni][2] = 0.f; acc[mi][ni][3] = 0.f;
        }

    gemm_main_bf16(g_ctx, g_wob, As, Bs, acc);

    const int tid  = threadIdx.x;
    const int lane = tid & 31;
    const int warp = tid >> 5;
    const int wm   = (warp >> 2) * 64;
    const int wn   = (warp & 3) * 32;
    const int g    = lane >> 2;
    const int q    = lane & 3;
    const int m0   = blockIdx.y * 128;
    const int n0   = blockIdx.x * 128;

    #pragma unroll
    for (int mi = 0; mi < 4; ++mi) {
        #pragma unroll
        for (int i = 0; i < 2; ++i) {
            const int gm = m0 + wm + mi * 16 + g + i * 8;
            #pragma unroll
            for (int ni = 0; ni < 4; ++ni) {
                const int gn0 = n0 + wn + ni * 8 + q * 2;
                const size_t off = (size_t)gm * Dm + gn0;
                const float2 r = *(const float2*)&x[off];
                float2 v;
                v.x = acc[mi][ni][i * 2 + 0] + bo[gn0 + 0] + r.x;
                v.y = acc[mi][ni][i * 2 + 1] + bo[gn0 + 1] + r.y;
                *(float2*)&g_y[off] = v;
            }
        }
    }
}

// ---------------------------------------------------------------------------
// Causal flash attention: 128-row q-tiles, double-buffered K/V cp.async,
// register-resident P (C-frag of S == A-frag of PV), exp2-domain softmax.
// grid = (16, 32), 256 thr. Dynamic smem: Ks[2], Vt[2] = 36864 B.
// ---------------------------------------------------------------------------
#define ALD 36
#define KV_WORDS (64 * ALD)
#define ATTN_SMEM_BYTES (4 * KV_WORDS * 4)   // 36864

__global__ void __launch_bounds__(256)
attn_kernel(const __nv_bfloat16* __restrict__ Qg, const __nv_bfloat16* __restrict__ Kg,
            const __nv_bfloat16* __restrict__ Vg, __nv_bfloat16* __restrict__ ctx)
{
    extern __shared__ uint32_t asmem[];
    uint32_t* KsB[2] = { asmem,                asmem + KV_WORDS };
    uint32_t* VtB[2] = { asmem + 2 * KV_WORDS, asmem + 3 * KV_WORDS };

    const int tid  = threadIdx.x;
    const int lane = tid & 31;
    const int warp = tid >> 5;
    const int g    = lane >> 2;
    const int q    = lane & 3;
    const int bh   = blockIdx.y;
    const int qb   = (int)(gridDim.x - 1) - (int)blockIdx.x;   // heavy first
    const int qi0  = qb * 128;
    const int wrow = warp * 16;

    const __nv_bfloat16* Qbh = Qg + (size_t)bh * Sm * DHm;
    const __nv_bfloat16* Kbh = Kg + (size_t)bh * Sm * DHm;
    const __nv_bfloat16* Vbh = Vg + (size_t)bh * DHm * Sm;

    // ldmatrix base addresses per buffer
    const int fr_row = (lane & 7) + ((lane & 16) >> 1);
    const int fr_wrd = (lane & 8) ? 4 : 0;
    uint32_t ks_b[2], vt_b[2];
    #pragma unroll
    for (int s = 0; s < 2; ++s) {
        ks_b[s] = cvta_s(&KsB[s][fr_row * ALD + fr_wrd]);
        vt_b[s] = cvta_s(&VtB[s][fr_row * ALD + fr_wrd]);
    }

    // cp.async fill positions (2 K + 2 V chunks per thread per tile)
    const int f_row0 = tid >> 3;            // rows 0..31
    const int f_row1 = (256 + tid) >> 3;    // rows 32..63
    const int f_cw   = tid & 7;
    uint32_t kdst[2][2], vdst[2][2];
    #pragma unroll
    for (int s = 0; s < 2; ++s) {
        kdst[s][0] = cvta_s(&KsB[s][f_row0 * ALD + f_cw * 4]);
        kdst[s][1] = cvta_s(&KsB[s][f_row1 * ALD + f_cw * 4]);
        vdst[s][0] = cvta_s(&VtB[s][f_row0 * ALD + f_cw * 4]);
        vdst[s][1] = cvta_s(&VtB[s][f_row1 * ALD + f_cw * 4]);
    }

    // Q fragments (pre-scaled by log2e/8)
    uint32_t qa[4][4];
    {
        const size_t r0 = (size_t)(qi0 + wrow + g) * DHm;
        const size_t r1 = r0 + 8 * DHm;
        #pragma unroll
        for (int kf = 0; kf < 4; ++kf) {
            const int d0 = kf * 16 + 2 * q;
            qa[kf][0] = *(const uint32_t*)&Qbh[r0 + d0];
            qa[kf][1] = *(const uint32_t*)&Qbh[r1 + d0];
            qa[kf][2] = *(const uint32_t*)&Qbh[r0 + d0 + 8];
            qa[kf][3] = *(const uint32_t*)&Qbh[r1 + d0 + 8];
        }
    }

    float m0 = -1e30f, m1 = -1e30f, l0 = 0.f, l1 = 0.f;
    float o[8][4];
    #pragma unroll
    for (int nf = 0; nf < 8; ++nf) {
        o[nf][0] = 0.f; o[nf][1] = 0.f; o[nf][2] = 0.f; o[nf][3] = 0.f;
    }

    const int ntiles = 2 * qb + 2;

    // prologue: fill tile 0 into buffer 0
    {
        CP16(kdst[0][0], Kbh + (size_t)f_row0 * DHm + f_cw * 8);
        CP16(kdst[0][1], Kbh + (size_t)f_row1 * DHm + f_cw * 8);
        CP16(vdst[0][0], Vbh + (size_t)f_row0 * Sm + f_cw * 8);
        CP16(vdst[0][1], Vbh + (size_t)f_row1 * Sm + f_cw * 8);
        CP_COMMIT();
    }

    for (int kt = 0; kt < ntiles; ++kt) {
        const int cur = kt & 1;
        CP_WAIT0();
        __syncthreads();

        if (kt + 1 < ntiles) {
            const int nxt = cur ^ 1;
            const int kj1 = (kt + 1) * 64;
            CP16(kdst[nxt][0], Kbh + (size_t)(kj1 + f_row0) * DHm + f_cw * 8);
            CP16(kdst[nxt][1], Kbh + (size_t)(kj1 + f_row1) * DHm + f_cw * 8);
            CP16(vdst[nxt][0], Vbh + (size_t)f_row0 * Sm + kj1 + f_cw * 8);
            CP16(vdst[nxt][1], Vbh + (size_t)f_row1 * Sm + kj1 + f_cw * 8);
            CP_COMMIT();
        }

        const int kj0 = kt * 64;

        // S = Q K^T  (log2 domain; per warp: 16 x 64)
        float sacc[8][4];
        #pragma unroll
        for (int nf = 0; nf < 8; ++nf) {
            sacc[nf][0] = 0.f; sacc[nf][1] = 0.f; sacc[nf][2] = 0.f; sacc[nf][3] = 0.f;
        }
        #pragma unroll
        for (int kf = 0; kf < 4; ++kf) {
            #pragma unroll
            for (int n2 = 0; n2 < 4; ++n2) {
                uint32_t b4[4];
                LDSM4(b4[0], b4[1], b4[2], b4[3],
                      ks_b[cur] + (n2 * 16 * ALD + kf * 8) * 4);
                mma_bf16(sacc[2 * n2],     qa[kf], b4);
                mma_bf16(sacc[2 * n2 + 1], qa[kf], b4 + 2);
            }
        }

        // causal mask (only last two tiles can be partial)
        if (kt >= 2 * qb) {
            const int rg0 = qi0 + wrow + g, rg1 = rg0 + 8;
            #pragma unroll
            for (int nf = 0; nf < 8; ++nf) {
                const int cg = kj0 + nf * 8 + 2 * q;
                if (cg     > rg0) sacc[nf][0] = -1e30f;
                if (cg + 1 > rg0) sacc[nf][1] = -1e30f;
                if (cg     > rg1) sacc[nf][2] = -1e30f;
                if (cg + 1 > rg1) sacc[nf][3] = -1e30f;
            }
        }

        // online softmax (log2 domain)
        float mx0 = -1e30f, mx1 = -1e30f;
        #pragma unroll
        for (int nf = 0; nf < 8; ++nf) {
            mx0 = fmaxf(mx0, fmaxf(sacc[nf][0], sacc[nf][1]));
            mx1 = fmaxf(mx1, fmaxf(sacc[nf][2], sacc[nf][3]));
        }
        mx0 = fmaxf(mx0, __shfl_xor_sync(0xffffffffu, mx0, 1));
        mx0 = fmaxf(mx0, __shfl_xor_sync(0xffffffffu, mx0, 2));
        mx1 = fmaxf(mx1, __shfl_xor_sync(0xffffffffu, mx1, 1));
        mx1 = fmaxf(mx1, __shfl_xor_sync(0xffffffffu, mx1, 2));

        const float mn0 = fmaxf(m0, mx0);
        const float mn1 = fmaxf(m1, mx1);
        const float al0 = ex2f(m0 - mn0);
        const float al1 = ex2f(m1 - mn1);
        m0 = mn0; m1 = mn1;

        float rs0 = 0.f, rs1 = 0.f;
        #pragma unroll
        for (int nf = 0; nf < 8; ++nf) {
            sacc[nf][0] = ex2f(sacc[nf][0] - mn0);
            sacc[nf][1] = ex2f(sacc[nf][1] - mn0);
            sacc[nf][2] = ex2f(sacc[nf][2] - mn1);
            sacc[nf][3] = ex2f(sacc[nf][3] - mn1);
            rs0 += sacc[nf][0] + sacc[nf][1];
            rs1 += sacc[nf][2] + sacc[nf][3];
        }
        rs0 += __shfl_xor_sync(0xffffffffu, rs0, 1);
        rs0 += __shfl_xor_sync(0xffffffffu, rs0, 2);
        rs1 += __shfl_xor_sync(0xffffffffu, rs1, 1);
        rs1 += __shfl_xor_sync(0xffffffffu, rs1, 2);

        l0 = l0 * al0 + rs0;
        l1 = l1 * al1 + rs1;
        #pragma unroll
        for (int nf = 0; nf < 8; ++nf) {
            o[nf][0] *= al0; o[nf][1] *= al0;
            o[nf][2] *= al1; o[nf][3] *= al1;
        }

        // O += P @ V ; P packed straight from sacc (C-frag == A-frag layout)
        #pragma unroll
        for (int kf = 0; kf < 4; ++kf) {
            uint32_t pa[4];
            pa[0] = pack_bf16(sacc[2 * kf][0],     sacc[2 * kf][1]);
            pa[1] = pack_bf16(sacc[2 * kf][2],     sacc[2 * kf][3]);
            pa[2] = pack_bf16(sacc[2 * kf + 1][0], sacc[2 * kf + 1][1]);
            pa[3] = pack_bf16(sacc[2 * kf + 1][2], sacc[2 * kf + 1][3]);
            #pragma unroll
            for (int n2 = 0; n2 < 4; ++n2) {
                uint32_t b4[4];
                LDSM4(b4[0], b4[1], b4[2], b4[3],
                      vt_b[cur] + (n2 * 16 * ALD + kf * 8) * 4);
                mma_bf16(o[2 * n2],     pa, b4);
                mma_bf16(o[2 * n2 + 1], pa, b4 + 2);
            }
        }
    }

    // epilogue
    const int b = bh >> 4, h = bh & 15;
    const float inv0 = 1.0f / l0;
    const float inv1 = 1.0f / l1;
    const int s0 = qi0 + wrow + g;
    #pragma unroll
    for (int nf = 0; nf < 8; ++nf) {
        const int dd = h * DHm + nf * 8 + 2 * q;
        *(uint32_t*)&ctx[((size_t)(b * Sm + s0)) * Dm + dd] =
            pack_bf16(o[nf][0] * inv0, o[nf][1] * inv0);
        *(uint32_t*)&ctx[((size_t)(b * Sm + s0 + 8)) * Dm + dd] =
            pack_bf16(o[nf][2] * inv1, o[nf][3] * inv1);
    }
}

// ---------------------------------------------------------------------------
// LayerNorm over last dim (1024).
// ---------------------------------------------------------------------------
__global__ void __launch_bounds__(256)
ln_kernel(const float* __restrict__ y, const float* __restrict__ gam,
          const float* __restrict__ bet, float* __restrict__ out)
{
    __shared__ float red[2][8];
    const int row = blockIdx.x;
    const int tid = threadIdx.x;

    const float4 v = *(const float4*)&y[(size_t)row * Dm + tid * 4];
    float s  = v.x + v.y + v.z + v.w;
    float ss = v.x * v.x + v.y * v.y + v.z * v.z + v.w * v.w;

    #pragma unroll
    for (int off = 16; off > 0; off >>= 1) {
        s  += __shfl_xor_sync(0xffffffffu, s, off);
        ss += __shfl_xor_sync(0xffffffffu, ss, off);
    }
    const int wid = tid >> 5, lane = tid & 31;
    if (lane == 0) { red[0][wid] = s; red[1][wid] = ss; }
    __syncthreads();
    if (tid == 0) {
        float S = 0.f, SS = 0.f;
        #pragma unroll
        for (int w = 0; w < 8; ++w) { S += red[0][w]; SS += red[1][w]; }
        red[0][0] = S; red[1][0] = SS;
    }
    __syncthreads();

    const float mu   = red[0][0] * (1.0f / Dm);
    const float var  = red[1][0] * (1.0f / Dm) - mu * mu;
    const float rstd = rsqrtf(var + 1e-5f);

    const float4 g4 = *(const float4*)&gam[tid * 4];
    const float4 b4 = *(const float4*)&bet[tid * 4];
    float4 r;
    r.x = (v.x - mu) * rstd * g4.x + b4.x;
    r.y = (v.y - mu) * rstd * g4.y + b4.y;
    r.z = (v.z - mu) * rstd * g4.z + b4.z;
    r.w = (v.w - mu) * rstd * g4.w + b4.w;
    *(float4*)&out[(size_t)row * Dm + tid * 4] = r;
}

// ---------------------------------------------------------------------------
extern "C" void kernel_launch(void* const* d_in, const int* in_sizes, int n_in,
                              void* d_out, int out_size)
{
    const float* x    = (const float*)d_in[0];
    const float* Wq   = (const float*)d_in[1];
    const float* bq   = (const float*)d_in[2];
    const float* Wk   = (const float*)d_in[3];
    const float* bk   = (const float*)d_in[4];
    const float* Wv   = (const float*)d_in[5];
    const float* bv   = (const float*)d_in[6];
    const float* Wo   = (const float*)d_in[7];
    const float* bo   = (const float*)d_in[8];
    const float* ln_g = (const float*)d_in[9];
    const float* ln_b = (const float*)d_in[10];
    float* out = (float*)d_out;

    __nv_bfloat16 *xb_p, *wq_p, *wk_p, *wv_p, *wo_p, *q_p, *k_p, *v_p, *ctx_p;
    float* y_p;
    cudaGetSymbolAddress((void**)&xb_p,  g_xb);
    cudaGetSymbolAddress((void**)&wq_p,  g_wqb);
    cudaGetSymbolAddress((void**)&wk_p,  g_wkb);
    cudaGetSymbolAddress((void**)&wv_p,  g_wvb);
    cudaGetSymbolAddress((void**)&wo_p,  g_wob);
    cudaGetSymbolAddress((void**)&q_p,   g_q);
    cudaGetSymbolAddress((void**)&k_p,   g_k);
    cudaGetSymbolAddress((void**)&v_p,   g_v);
    cudaGetSymbolAddress((void**)&ctx_p, g_ctx);
    cudaGetSymbolAddress((void**)&y_p,   g_y);

    cudaFuncSetAttribute(gemm_qkv_kernel,
                         cudaFuncAttributeMaxDynamicSharedMemorySize, GEMM_SMEM_BYTES);
    cudaFuncSetAttribute(gemm_oproj_kernel,
                         cudaFuncAttributeMaxDynamicSharedMemorySize, GEMM_SMEM_BYTES);
    cudaFuncSetAttribute(attn_kernel,
                         cudaFuncAttributeMaxDynamicSharedMemorySize, ATTN_SMEM_BYTES);

    const int nx4 = Bm * Sm * Dm / 4;
    const int nw4 = Dm * Dm / 4;
    to_bf16_kernel<<<(nx4 + 255) / 256, 256>>>(x, xb_p, nx4);
    to_bf16_w4_kernel<<<dim3((nw4 + 255) / 256, 1, 4), 256>>>(
        Wq, Wk, Wv, Wo, wq_p, wk_p, wv_p, wo_p, nw4);

    gemm_qkv_kernel<<<dim3(8, 32, 3), 256, GEMM_SMEM_BYTES>>>(bq, bk, bv);
    attn_kernel<<<dim3(16, 32), 256, ATTN_SMEM_BYTES>>>(q_p, k_p, v_p, ctx_p);
    gemm_oproj_kernel<<<dim3(8, 32), 256, GEMM_SMEM_BYTES>>>(bo, x);
    ln_kernel<<<4096, 256>>>(y_p, ln_g, ln_b, out);
}